// round 2
// baseline (speedup 1.0000x reference)
#include <cuda_runtime.h>
#include <cstdint>

#define N_CAP 50000
#define D 128
#define F_IN 256
#define C_ATT 32

typedef unsigned long long ull;

// -------- device scratch (no runtime allocation allowed) --------
__device__ float g_l_gene[N_CAP * D];
__device__ float g_r_gene[N_CAP * D];
__device__ float g_l_prot[N_CAP * D];
__device__ float g_r_prot[N_CAP * D];
__device__ float g_agg_gg[N_CAP * D];
__device__ float g_agg_gp[N_CAP * D];
__device__ float g_agg_pp[N_CAP * D];
__device__ float g_s[6 * N_CAP];      // sl0,sr0,sl1,sr1,sl2,sr2
__device__ float g_denom[3 * N_CAP];

// -------- packed f32x2 helpers (sm_100+) --------
__device__ __forceinline__ ull pack2(float a) {
    ull r;
    asm("mov.b64 %0, {%1, %1};" : "=l"(r) : "f"(a));
    return r;
}
__device__ __forceinline__ void fma2(ull& c, ull a, ull b) {
    asm("fma.rn.f32x2 %0, %1, %2, %0;" : "+l"(c) : "l"(a), "l"(b));
}

// ================= projection GEMM =================
// out[N,128] = X[N,256] @ W[128,256]^T + bias ; grid.y selects (Wl)/(Wr)
#define BM 128
#define BN 128
#define BK 16

__global__ __launch_bounds__(256) void proj_gemm(
    const float* __restrict__ X, int N,
    const float* __restrict__ Wl, const float* __restrict__ bl, float* __restrict__ outL,
    const float* __restrict__ Wr, const float* __restrict__ br, float* __restrict__ outR)
{
    const float* W    = blockIdx.y ? Wr : Wl;
    const float* bias = blockIdx.y ? br : bl;
    float* out        = blockIdx.y ? outR : outL;

    __shared__ float As[BK][BM + 4];
    __shared__ float Bs[BK][BN + 4];

    int t  = threadIdx.x;
    int m0 = blockIdx.x * BM;
    int tx = t & 15, ty = t >> 4;
    int lr = t >> 2;
    int lc = (t & 3) * 4;

    ull acc[8][4];
#pragma unroll
    for (int i = 0; i < 8; i++)
#pragma unroll
        for (int j = 0; j < 4; j++) acc[i][j] = 0ull;

    for (int kt = 0; kt < F_IN; kt += BK) {
#pragma unroll
        for (int p = 0; p < 2; ++p) {
            int m  = lr + p * 64;
            int gm = m0 + m; if (gm >= N) gm = N - 1;
            float4 v = *(const float4*)(X + (size_t)gm * F_IN + kt + lc);
            As[lc + 0][m] = v.x; As[lc + 1][m] = v.y;
            As[lc + 2][m] = v.z; As[lc + 3][m] = v.w;
            int n = lr + p * 64;
            float4 w = *(const float4*)(W + (size_t)n * F_IN + kt + lc);
            Bs[lc + 0][n] = w.x; Bs[lc + 1][n] = w.y;
            Bs[lc + 2][n] = w.z; Bs[lc + 3][n] = w.w;
        }
        __syncthreads();
#pragma unroll
        for (int kk = 0; kk < BK; kk++) {
            float4 a0 = *(const float4*)&As[kk][ty * 8];
            float4 a1 = *(const float4*)&As[kk][ty * 8 + 4];
            ulonglong2 bA = *(const ulonglong2*)&Bs[kk][tx * 8];
            ulonglong2 bB = *(const ulonglong2*)&Bs[kk][tx * 8 + 4];
            ull b0 = bA.x, b1 = bA.y, b2 = bB.x, b3 = bB.y;
            float av[8] = {a0.x, a0.y, a0.z, a0.w, a1.x, a1.y, a1.z, a1.w};
#pragma unroll
            for (int i = 0; i < 8; i++) {
                ull aa = pack2(av[i]);
                fma2(acc[i][0], aa, b0);
                fma2(acc[i][1], aa, b1);
                fma2(acc[i][2], aa, b2);
                fma2(acc[i][3], aa, b3);
            }
        }
        __syncthreads();
    }

    float bi[8];
    {
        float4 q0 = *(const float4*)(bias + tx * 8);
        float4 q1 = *(const float4*)(bias + tx * 8 + 4);
        bi[0] = q0.x; bi[1] = q0.y; bi[2] = q0.z; bi[3] = q0.w;
        bi[4] = q1.x; bi[5] = q1.y; bi[6] = q1.z; bi[7] = q1.w;
    }
#pragma unroll
    for (int i = 0; i < 8; i++) {
        int row = m0 + ty * 8 + i;
        if (row < N) {
            union { ull u; float2 f; } cv;
            float o[8];
#pragma unroll
            for (int j = 0; j < 4; j++) {
                cv.u = acc[i][j];
                o[2 * j]     = cv.f.x + bi[2 * j];
                o[2 * j + 1] = cv.f.y + bi[2 * j + 1];
            }
            *(float4*)(out + (size_t)row * D + tx * 8)     = make_float4(o[0], o[1], o[2], o[3]);
            *(float4*)(out + (size_t)row * D + tx * 8 + 4) = make_float4(o[4], o[5], o[6], o[7]);
        }
    }
}

// ================= per-node attention scalar =================
// s[n] = sum_c tanh( W[c,:] . feat[n,:] + b[c] ) * q[c]   (c = lane, warp per node)
__global__ __launch_bounds__(128) void attn_scalar(
    const float* __restrict__ feat, int N,
    const float* __restrict__ W, const float* __restrict__ b,
    const float* __restrict__ q, float* __restrict__ s_out)
{
    __shared__ float Ws[C_ATT][D + 4];
    __shared__ float fs[4][D];
    int t = threadIdx.x;
    for (int i = t; i < C_ATT * D; i += 128) Ws[i >> 7][i & 127] = W[i];
    __syncthreads();
    int warp = t >> 5, lane = t & 31;
    float qc = q[lane], bc = b[lane];
    for (int n = blockIdx.x * 4 + warp; n < N; n += gridDim.x * 4) {
        *(float4*)&fs[warp][lane * 4] = *(const float4*)(feat + (size_t)n * D + lane * 4);
        __syncwarp();
        ull acc2 = 0ull;
#pragma unroll
        for (int k = 0; k < D; k += 4) {
            ulonglong2 f2 = *(const ulonglong2*)&fs[warp][k];
            ulonglong2 w2 = *(const ulonglong2*)&Ws[lane][k];
            fma2(acc2, w2.x, f2.x);
            fma2(acc2, w2.y, f2.y);
        }
        union { ull u; float2 f; } cv; cv.u = acc2;
        float acc = cv.f.x + cv.f.y + bc;
        float sv = tanhf(acc) * qc;
#pragma unroll
        for (int o = 16; o; o >>= 1) sv += __shfl_xor_sync(0xffffffffu, sv, o);
        if (lane == 0) s_out[n] = sv;
        __syncwarp();
    }
}

// ================= edge passes =================
// |e| <= sum|qw| < 20, so exp never overflows fp32: skip the segment-max pass.
__global__ __launch_bounds__(256) void edge_denom(
    const int* __restrict__ eidx, int E,
    const float* __restrict__ sl, const float* __restrict__ sr,
    const float* __restrict__ sharp, int mp, float* __restrict__ denom)
{
    int i = blockIdx.x * 256 + threadIdx.x;
    if (i >= E) return;
    int s = eidx[i], d2 = eidx[E + i];
    float e = (sl[s] + sr[d2]) * sharp[mp];
    atomicAdd(&denom[s], __expf(e));
}

__global__ __launch_bounds__(256) void edge_scatter(
    const int* __restrict__ eidx, int E,
    const float* __restrict__ sl, const float* __restrict__ sr,
    const float* __restrict__ sharp, int mp, const float* __restrict__ denom,
    const float* __restrict__ rtail, float* __restrict__ agg)
{
    int g = blockIdx.x * 256 + threadIdx.x;
    int w = g >> 5, lane = g & 31;
    if (w >= E) return;
    int s = eidx[w], d = eidx[E + w];
    float e = (sl[s] + sr[d]) * sharp[mp];
    float alpha = __expf(e) / (denom[s] + 1e-16f);
    float4 v = *(const float4*)(rtail + (size_t)d * D + lane * 4);
    v.x *= alpha; v.y *= alpha; v.z *= alpha; v.w *= alpha;
    float* p = agg + (size_t)s * D + lane * 4;
    asm volatile("red.global.add.v4.f32 [%0], {%1,%2,%3,%4};"
                 :: "l"(p), "f"(v.x), "f"(v.y), "f"(v.z), "f"(v.w) : "memory");
}

// ================= relation combine =================
__global__ __launch_bounds__(256) void combine_kernel(
    const float* __restrict__ a0, const float* __restrict__ a1,
    const float* __restrict__ selfe,
    const float* __restrict__ convW,
    float* __restrict__ out, int N, int two)
{
    int g = blockIdx.x * 256 + threadIdx.x;
    int w = g >> 5, lane = g & 31;
    if (w >= N) return;
    size_t off = (size_t)w * D + lane * 4;
    float4 cw = *(const float4*)(convW + lane * 4);
    float4 r0 = *(const float4*)(a0 + off);
    float4 r1 = make_float4(0.f, 0.f, 0.f, 0.f);
    if (two) r1 = *(const float4*)(a1 + off);
    float4 rs = *(const float4*)(selfe + off);
    float d0 = cw.x * r0.x + cw.y * r0.y + cw.z * r0.z + cw.w * r0.w;
    float d1 = cw.x * r1.x + cw.y * r1.y + cw.z * r1.z + cw.w * r1.w;
    float ds = cw.x * rs.x + cw.y * rs.y + cw.z * rs.z + cw.w * rs.w;
#pragma unroll
    for (int o = 16; o; o >>= 1) {
        d0 += __shfl_xor_sync(0xffffffffu, d0, o);
        d1 += __shfl_xor_sync(0xffffffffu, d1, o);
        ds += __shfl_xor_sync(0xffffffffu, ds, o);
    }
    // conv bias is identical across relations -> cancels in softmax exactly
    float m = fmaxf(d0, ds);
    if (two) m = fmaxf(m, d1);
    float e0 = __expf(d0 - m);
    float e1 = two ? __expf(d1 - m) : 0.f;
    float es = __expf(ds - m);
    float inv = 1.f / (e0 + e1 + es);
    e0 *= inv; e1 *= inv; es *= inv;
    float4 o4;
    o4.x = fmaxf(0.f, r0.x * e0 + r1.x * e1 + rs.x * es);
    o4.y = fmaxf(0.f, r0.y * e0 + r1.y * e1 + rs.y * es);
    o4.z = fmaxf(0.f, r0.z * e0 + r1.z * e1 + rs.z * es);
    o4.w = fmaxf(0.f, r0.w * e0 + r1.w * e1 + rs.w * es);
    *(float4*)(out + off) = o4;
}

// ================= launcher =================
extern "C" void kernel_launch(void* const* d_in, const int* in_sizes, int n_in,
                              void* d_out, int out_size)
{
    const float* x_gene  = (const float*)d_in[0];
    const float* x_prot  = (const float*)d_in[1];
    const float* Wl_gene = (const float*)d_in[2];
    const float* bl_gene = (const float*)d_in[3];
    const float* Wr_gene = (const float*)d_in[4];
    const float* br_gene = (const float*)d_in[5];
    const float* Wl_prot = (const float*)d_in[6];
    const float* bl_prot = (const float*)d_in[7];
    const float* Wr_prot = (const float*)d_in[8];
    const float* br_prot = (const float*)d_in[9];
    const float* alW     = (const float*)d_in[10];
    const float* alb     = (const float*)d_in[11];
    const float* arW     = (const float*)d_in[12];
    const float* arb     = (const float*)d_in[13];
    const float* qw      = (const float*)d_in[14];
    const float* sharp   = (const float*)d_in[15];
    const float* convgW  = (const float*)d_in[16];
    const float* convpW  = (const float*)d_in[18];
    const int*   e_gg    = (const int*)d_in[20];
    const int*   e_gp    = (const int*)d_in[21];
    const int*   e_pp    = (const int*)d_in[22];

    int Ng  = in_sizes[0] / F_IN;
    int Np  = in_sizes[1] / F_IN;
    int Egg = in_sizes[20] / 2;
    int Egp = in_sizes[21] / 2;
    int Epp = in_sizes[22] / 2;

    float *l_gene, *r_gene, *l_prot, *r_prot, *agg_gg, *agg_gp, *agg_pp, *sbuf, *dbuf;
    cudaGetSymbolAddress((void**)&l_gene, g_l_gene);
    cudaGetSymbolAddress((void**)&r_gene, g_r_gene);
    cudaGetSymbolAddress((void**)&l_prot, g_l_prot);
    cudaGetSymbolAddress((void**)&r_prot, g_r_prot);
    cudaGetSymbolAddress((void**)&agg_gg, g_agg_gg);
    cudaGetSymbolAddress((void**)&agg_gp, g_agg_gp);
    cudaGetSymbolAddress((void**)&agg_pp, g_agg_pp);
    cudaGetSymbolAddress((void**)&sbuf, g_s);
    cudaGetSymbolAddress((void**)&dbuf, g_denom);

    float* sl0 = sbuf + 0 * N_CAP; float* sr0 = sbuf + 1 * N_CAP;
    float* sl1 = sbuf + 2 * N_CAP; float* sr1 = sbuf + 3 * N_CAP;
    float* sl2 = sbuf + 4 * N_CAP; float* sr2 = sbuf + 5 * N_CAP;
    float* den0 = dbuf; float* den1 = dbuf + N_CAP; float* den2 = dbuf + 2 * N_CAP;

    cudaMemsetAsync(agg_gg, 0, (size_t)Ng * D * sizeof(float), 0);
    cudaMemsetAsync(agg_gp, 0, (size_t)Ng * D * sizeof(float), 0);
    cudaMemsetAsync(agg_pp, 0, (size_t)Np * D * sizeof(float), 0);
    cudaMemsetAsync(den0, 0, (size_t)Ng * sizeof(float), 0);
    cudaMemsetAsync(den1, 0, (size_t)Ng * sizeof(float), 0);
    cudaMemsetAsync(den2, 0, (size_t)Np * sizeof(float), 0);

    proj_gemm<<<dim3((Ng + BM - 1) / BM, 2), 256>>>(x_gene, Ng, Wl_gene, bl_gene, l_gene,
                                                    Wr_gene, br_gene, r_gene);
    proj_gemm<<<dim3((Np + BM - 1) / BM, 2), 256>>>(x_prot, Np, Wl_prot, bl_prot, l_prot,
                                                    Wr_prot, br_prot, r_prot);

    attn_scalar<<<1184, 128>>>(l_gene, Ng, alW + 0 * C_ATT * D, alb + 0 * C_ATT, qw + 0 * 64,          sl0);
    attn_scalar<<<1184, 128>>>(r_gene, Ng, arW + 0 * C_ATT * D, arb + 0 * C_ATT, qw + 0 * 64 + C_ATT,  sr0);
    attn_scalar<<<1184, 128>>>(l_gene, Ng, alW + 1 * C_ATT * D, alb + 1 * C_ATT, qw + 1 * 64,          sl1);
    attn_scalar<<<1184, 128>>>(r_prot, Np, arW + 1 * C_ATT * D, arb + 1 * C_ATT, qw + 1 * 64 + C_ATT,  sr1);
    attn_scalar<<<1184, 128>>>(l_prot, Np, alW + 2 * C_ATT * D, alb + 2 * C_ATT, qw + 2 * 64,          sl2);
    attn_scalar<<<1184, 128>>>(r_prot, Np, arW + 2 * C_ATT * D, arb + 2 * C_ATT, qw + 2 * 64 + C_ATT,  sr2);

    edge_denom<<<(Egg + 255) / 256, 256>>>(e_gg, Egg, sl0, sr0, sharp, 0, den0);
    edge_denom<<<(Egp + 255) / 256, 256>>>(e_gp, Egp, sl1, sr1, sharp, 1, den1);
    edge_denom<<<(Epp + 255) / 256, 256>>>(e_pp, Epp, sl2, sr2, sharp, 2, den2);

    edge_scatter<<<(unsigned)(((size_t)Egg * 32 + 255) / 256), 256>>>(e_gg, Egg, sl0, sr0, sharp, 0, den0, r_gene, agg_gg);
    edge_scatter<<<(unsigned)(((size_t)Egp * 32 + 255) / 256), 256>>>(e_gp, Egp, sl1, sr1, sharp, 1, den1, r_prot, agg_gp);
    edge_scatter<<<(unsigned)(((size_t)Epp * 32 + 255) / 256), 256>>>(e_pp, Epp, sl2, sr2, sharp, 2, den2, r_prot, agg_pp);

    float* out = (float*)d_out;
    combine_kernel<<<(unsigned)(((size_t)Ng * 32 + 255) / 256), 256>>>(agg_gg, agg_gp, l_gene, convgW, out, Ng, 1);
    combine_kernel<<<(unsigned)(((size_t)Np * 32 + 255) / 256), 256>>>(agg_pp, agg_pp, l_prot, convpW, out + (size_t)Ng * D, Np, 0);
}